// round 11
// baseline (speedup 1.0000x reference)
#include <cuda_runtime.h>
#include <math.h>

#define N_WL 262144
#define NV4  (N_WL / 4)

// ---------------- compile-time line constants (from reference LINES/MASS) -------------
__constant__ float c_nu0[10]  = {254.0f, 280.0f, 310.0f, 940.0f, 1130.0f,
                                 1380.0f, 1400.0f, 1600.0f, 2000.0f, 2700.0f};
__constant__ float c_str[10]  = {1.15e-17f, 5e-18f, 1.9e-19f, 2.5e-23f, 8.2e-24f,
                                 1.8e-22f, 3.5e-25f, 7.8e-26f, 4.2e-24f, 1.2e-24f};
__constant__ float c_wid[10]  = {2.0f, 3.0f, 2.5f, 3.0f, 2.5f, 4.0f, 3.0f, 2.5f, 4.0f, 3.5f};
__constant__ float c_tex[10]  = {0.05f, 0.04f, 0.03f, 0.4f, 0.35f, 0.45f, 0.5f, 0.48f, 0.52f, 0.49f};
__constant__ float c_mass[10] = {48.f, 48.f, 48.f, 18.f, 18.f, 18.f, 44.f, 44.f, 44.f, 44.f};

// ---------------- device-global scratch ----------------------------------------------
__device__ float g_nu0[10], g_is[10], g_y[10], g_amp[10];
__device__ float g_h[32];
__device__ float g_m2[64];

// ---------------- math helpers --------------------------------------------------------
__device__ __forceinline__ float voigt_core(float x, float y) {
    float ax = fabsf(x);
    float s  = ax + y;
    float x2 = x * x;
    float y2 = y * y;
    if (s >= 15.0f) {
        float dr = 0.5f + y2 - x2;
        float di = -2.0f * x * y;
        float num = y * dr + 2.0f * x2 * y;
        return 0.5641896f * num / (dr * dr + di * di);
    } else if (ax >= 5.5f) {
        float ur = y2 - x2;
        float ui = -2.0f * x * y;
        float Ar = 1.410474f + 0.5641896f * ur;
        float Ai = 0.5641896f * ui;
        float nr = y * Ar + x * Ai;
        float ni = y * Ai - x * Ar;
        float dr = 0.75f + 3.0f * ur + (ur * ur - ui * ui);
        float di = 3.0f * ui + 2.0f * ur * ui;
        return (nr * dr + ni * di) / (dr * dr + di * di);
    } else {
        return expf(-x2) * cosf(2.0f * x * y) * 0.5641895835f
             + 0.6366197723f * y * sinf(x2) / (x2 + y2 + 1e-10f);
    }
}

__device__ __forceinline__ float softplus_f(float z) {
    return fmaxf(z, 0.0f) + log1pf(expf(-fabsf(z)));
}
__device__ __forceinline__ float sigmoid_f(float z) {
    return 1.0f / (1.0f + expf(-z));
}
__device__ __forceinline__ float silu_f(float z) {
    return z * sigmoid_f(z);
}

// ---------------- kernel 1: sequential prep (1 block, 64 threads) ---------------------
__global__ void prep_kernel(
    const float* __restrict__ wl,
    const float* __restrict__ Tp,  const float* __restrict__ Pp,
    const float* __restrict__ o3p, const float* __restrict__ h2op, const float* __restrict__ co2p,
    const float* __restrict__ mw1, const float* __restrict__ mb1,
    const float* __restrict__ mw2, const float* __restrict__ mb2,
    const float* __restrict__ cw1, const float* __restrict__ cb1,
    const float* __restrict__ cw2, const float* __restrict__ cb2)
{
    __shared__ float s_nu0[10], s_is[10], s_y[10], s_amp[10];
    __shared__ float s_h[32], s_mf[10], s_m1[64];

    const int t = threadIdx.x;
    const float T = Tp[0];
    const float P = Pp[0];
    const float invT = 273.15f / (T + 1e-12f);

    if (t < 10) {
        float sT    = c_str[t] * powf(invT, c_tex[t]);
        float gL    = c_wid[t] * (P / (101325.0f + 1e-12f)) * sqrtf(invT);
        float gD    = c_nu0[t] / 299792458.0f *
                      sqrtf(2.0f * 1.380649e-23f * T * 6.02214076e23f / (c_mass[t] + 1e-12f));
        float sigma = gD / (1.1774100f + 1e-12f);
        float conc  = (t < 3) ? o3p[0] : ((t < 6) ? h2op[0] : co2p[0]);
        float is    = 1.0f / (sigma + 1e-12f);
        float yv    = gL * is;
        float amp   = conc * sT / (sigma * 1.7724539f + 1e-12f);
        s_nu0[t] = c_nu0[t];  s_is[t] = is;  s_y[t] = yv;  s_amp[t] = amp;
        g_nu0[t] = c_nu0[t];  g_is[t] = is;  g_y[t] = yv;  g_amp[t] = amp;
    }

    if (t < 32) {
        float z = cb1[t];
        z = fmaf(T / (273.15f + 1e-12f),   cw1[0 * 32 + t], z);
        z = fmaf(P / (101325.0f + 1e-12f), cw1[1 * 32 + t], z);
        z = fmaf(h2op[0],                  cw1[2 * 32 + t], z);
        z = fmaf(1.0f,                     cw1[3 * 32 + t], z);
        float h = silu_f(z);
        s_h[t] = h;
        g_h[t] = h;
    }
    __syncthreads();

    if (t < 8) {
        float w = wl[t];
        float c = 0.0f;
        #pragma unroll
        for (int l = 0; l < 10; l++) {
            float x = (w - s_nu0[l]) * s_is[l];
            c = fmaf(s_amp[l], voigt_core(x, s_y[l]), c);
        }
        float z = cb2[t];
        #pragma unroll
        for (int k = 0; k < 32; k++)
            z = fmaf(s_h[k], cw2[k * N_WL + t], z);
        s_mf[2 + t] = c + softplus_f(z);
    }
    if (t == 0) {
        s_mf[0] = T / (273.15f + 1e-12f);
        s_mf[1] = P / (101325.0f + 1e-12f);
    }
    __syncthreads();

    if (t < 64) {
        float z = mb1[t];
        #pragma unroll
        for (int j = 0; j < 10; j++)
            z = fmaf(s_mf[j], mw1[j * 64 + t], z);
        s_m1[t] = silu_f(z);
    }
    __syncthreads();

    if (t < 64) {
        float z = mb2[t];
        #pragma unroll
        for (int j = 0; j < 64; j++)
            z = fmaf(s_m1[j], mw2[j * 64 + t], z);
        g_m2[t] = silu_f(z);
    }
}

// ---------------- kernel 2: split-K streaming pass -------------------------------------
// float4 accesses (proven best), 512 blocks x 256 threads. Threads t<128 and t>=128
// cover the SAME 128 float4 wavelengths but DIFFERENT halves of the k-rows, doubling
// resident warps at identical per-warp load width/depth. Partials combine via smem.
__global__ __launch_bounds__(256, 4) void spec_kernel(
    const float4* __restrict__ wl,
    const float4* __restrict__ cont_w2, const float4* __restrict__ cont_b2,
    const float4* __restrict__ mix_w3,  const float4* __restrict__ mix_b3,
    float4* __restrict__ out)
{
    __shared__ float s_nu0[10], s_is[10], s_y[10], s_amp[10];
    __shared__ float s_h[32], s_m[64];
    __shared__ float4 sh_a[128];   // half-1 continuum partials
    __shared__ float4 sh_z[128];   // half-1 mixing partials
    __shared__ float4 sh_cr[128];  // half-1 Voigt sums

    const int t    = threadIdx.x;
    const int lane = t & 127;
    const int half = t >> 7;

    if (t < 10) { s_nu0[t] = g_nu0[t]; s_is[t] = g_is[t]; s_y[t] = g_y[t]; s_amp[t] = g_amp[t]; }
    if (t >= 32 && t < 64) s_h[t - 32] = g_h[t - 32];
    if (t >= 64 && t < 128) s_m[t - 64] = g_m2[t - 64];
    __syncthreads();

    const int i = blockIdx.x * 128 + lane;   // 0 .. NV4-1

    // ---- k-row ranges per half ----
    const int ck0 = half ? 16 : 0;    // continuum rows [ck0, ck0+16)
    const int mk0 = half ? 32 : 0;    // mixing rows   [mk0, mk0+32)

    // ---- continuum partial: 16 rows in two 8-deep batches ----
    float4 a  = half ? make_float4(0.f, 0.f, 0.f, 0.f) : cont_b2[i];
    float4 a1 = make_float4(0.f, 0.f, 0.f, 0.f);
    #pragma unroll
    for (int kk = 0; kk < 16; kk += 8) {
        float4 v[8];
        #pragma unroll
        for (int j = 0; j < 8; j++)
            v[j] = cont_w2[(ck0 + kk + j) * NV4 + i];
        #pragma unroll
        for (int j = 0; j < 8; j += 2) {
            float h0 = s_h[ck0 + kk + j], h1 = s_h[ck0 + kk + j + 1];
            a.x  = fmaf(h0, v[j].x,     a.x);
            a.y  = fmaf(h0, v[j].y,     a.y);
            a.z  = fmaf(h0, v[j].z,     a.z);
            a.w  = fmaf(h0, v[j].w,     a.w);
            a1.x = fmaf(h1, v[j + 1].x, a1.x);
            a1.y = fmaf(h1, v[j + 1].y, a1.y);
            a1.z = fmaf(h1, v[j + 1].z, a1.z);
            a1.w = fmaf(h1, v[j + 1].w, a1.w);
        }
    }
    a.x += a1.x;  a.y += a1.y;  a.z += a1.z;  a.w += a1.w;

    // ---- mixing partial: 32 rows in four 8-deep batches ----
    float4 z  = half ? make_float4(0.f, 0.f, 0.f, 0.f) : mix_b3[i];
    float4 z1 = make_float4(0.f, 0.f, 0.f, 0.f);
    #pragma unroll
    for (int kk = 0; kk < 32; kk += 8) {
        float4 v[8];
        #pragma unroll
        for (int j = 0; j < 8; j++)
            v[j] = mix_w3[(mk0 + kk + j) * NV4 + i];
        #pragma unroll
        for (int j = 0; j < 8; j += 2) {
            float m0 = s_m[mk0 + kk + j], m1 = s_m[mk0 + kk + j + 1];
            z.x  = fmaf(m0, v[j].x,     z.x);
            z.y  = fmaf(m0, v[j].y,     z.y);
            z.z  = fmaf(m0, v[j].z,     z.z);
            z.w  = fmaf(m0, v[j].w,     z.w);
            z1.x = fmaf(m1, v[j + 1].x, z1.x);
            z1.y = fmaf(m1, v[j + 1].y, z1.y);
            z1.z = fmaf(m1, v[j + 1].z, z1.z);
            z1.w = fmaf(m1, v[j + 1].w, z1.w);
        }
    }
    z.x += z1.x;  z.y += z1.y;  z.z += z1.z;  z.w += z1.w;

    if (half) {
        // half 1 additionally computes the Voigt line sum for these wavelengths
        float4 w4 = wl[i];
        float wv[4] = {w4.x, w4.y, w4.z, w4.w};
        float cr[4] = {0.f, 0.f, 0.f, 0.f};
        #pragma unroll 1
        for (int l = 0; l < 10; l++) {
            float nu0 = s_nu0[l], is = s_is[l], y = s_y[l], amp = s_amp[l];
            #pragma unroll
            for (int j = 0; j < 4; j++) {
                float x = (wv[j] - nu0) * is;
                cr[j] = fmaf(amp, voigt_core(x, y), cr[j]);
            }
        }
        sh_a[lane]  = a;
        sh_z[lane]  = z;
        sh_cr[lane] = make_float4(cr[0], cr[1], cr[2], cr[3]);
    }
    __syncthreads();

    if (!half) {
        float4 ab = sh_a[lane];
        float4 zb = sh_z[lane];
        float4 cr = sh_cr[lane];

        float c0 = cr.x + softplus_f(a.x + ab.x);
        float c1 = cr.y + softplus_f(a.y + ab.y);
        float c2 = cr.z + softplus_f(a.z + ab.z);
        float c3 = cr.w + softplus_f(a.w + ab.w);

        float4 o;
        o.x = c0 * (1.0f + 0.1f * (sigmoid_f(z.x + zb.x) - 0.5f));
        o.y = c1 * (1.0f + 0.1f * (sigmoid_f(z.y + zb.y) - 0.5f));
        o.z = c2 * (1.0f + 0.1f * (sigmoid_f(z.z + zb.z) - 0.5f));
        o.w = c3 * (1.0f + 0.1f * (sigmoid_f(z.w + zb.w) - 0.5f));
        out[i] = o;
    }
}

// ---------------- launch --------------------------------------------------------------
extern "C" void kernel_launch(void* const* d_in, const int* in_sizes, int n_in,
                              void* d_out, int out_size)
{
    const float* wl   = (const float*)d_in[0];
    const float* Tp   = (const float*)d_in[1];
    const float* Pp   = (const float*)d_in[2];
    const float* o3   = (const float*)d_in[3];
    const float* h2o  = (const float*)d_in[4];
    const float* co2  = (const float*)d_in[5];
    const float* mw1  = (const float*)d_in[6];
    const float* mb1  = (const float*)d_in[7];
    const float* mw2  = (const float*)d_in[8];
    const float* mb2  = (const float*)d_in[9];
    const float* mw3  = (const float*)d_in[10];
    const float* mb3  = (const float*)d_in[11];
    const float* cw1  = (const float*)d_in[12];
    const float* cb1  = (const float*)d_in[13];
    const float* cw2  = (const float*)d_in[14];
    const float* cb2  = (const float*)d_in[15];

    prep_kernel<<<1, 64>>>(wl, Tp, Pp, o3, h2o, co2,
                           mw1, mb1, mw2, mb2, cw1, cb1, cw2, cb2);

    spec_kernel<<<NV4 / 128, 256>>>(
        (const float4*)wl,
        (const float4*)cw2, (const float4*)cb2,
        (const float4*)mw3, (const float4*)mb3,
        (float4*)d_out);
}

// round 13
// speedup vs baseline: 1.4040x; 1.4040x over previous
#include <cuda_runtime.h>
#include <math.h>

#define N_WL   262144
#define TILE   256              // floats per block tile
#define NBLK   (N_WL / TILE)    // 1024 blocks
#define NROWS  96               // 32 cont rows + 64 mix rows
#define NR     12               // rows per pipeline stage
#define NPH    (NROWS / NR)     // 8 phases
#define STAGE_BYTES (NR * TILE * 4)   // 12288

// ---------------- compile-time line constants (from reference LINES/MASS) -------------
__constant__ float c_nu0[10]  = {254.0f, 280.0f, 310.0f, 940.0f, 1130.0f,
                                 1380.0f, 1400.0f, 1600.0f, 2000.0f, 2700.0f};
__constant__ float c_str[10]  = {1.15e-17f, 5e-18f, 1.9e-19f, 2.5e-23f, 8.2e-24f,
                                 1.8e-22f, 3.5e-25f, 7.8e-26f, 4.2e-24f, 1.2e-24f};
__constant__ float c_wid[10]  = {2.0f, 3.0f, 2.5f, 3.0f, 2.5f, 4.0f, 3.0f, 2.5f, 4.0f, 3.5f};
__constant__ float c_tex[10]  = {0.05f, 0.04f, 0.03f, 0.4f, 0.35f, 0.45f, 0.5f, 0.48f, 0.52f, 0.49f};
__constant__ float c_mass[10] = {48.f, 48.f, 48.f, 18.f, 18.f, 18.f, 44.f, 44.f, 44.f, 44.f};

// ---------------- device-global scratch ----------------------------------------------
__device__ float g_nu0[10], g_is[10], g_y[10], g_amp[10];
__device__ float g_h[32];
__device__ float g_m2[64];

// ---------------- math helpers --------------------------------------------------------
__device__ __forceinline__ float voigt_core(float x, float y) {
    float ax = fabsf(x);
    float s  = ax + y;
    float x2 = x * x;
    float y2 = y * y;
    if (s >= 15.0f) {
        float dr = 0.5f + y2 - x2;
        float di = -2.0f * x * y;
        float num = y * dr + 2.0f * x2 * y;
        return 0.5641896f * num / (dr * dr + di * di);
    } else if (ax >= 5.5f) {
        float ur = y2 - x2;
        float ui = -2.0f * x * y;
        float Ar = 1.410474f + 0.5641896f * ur;
        float Ai = 0.5641896f * ui;
        float nr = y * Ar + x * Ai;
        float ni = y * Ai - x * Ar;
        float dr = 0.75f + 3.0f * ur + (ur * ur - ui * ui);
        float di = 3.0f * ui + 2.0f * ur * ui;
        return (nr * dr + ni * di) / (dr * dr + di * di);
    } else {
        return expf(-x2) * cosf(2.0f * x * y) * 0.5641895835f
             + 0.6366197723f * y * sinf(x2) / (x2 + y2 + 1e-10f);
    }
}

__device__ __forceinline__ float softplus_f(float z) {
    return fmaxf(z, 0.0f) + log1pf(expf(-fabsf(z)));
}
__device__ __forceinline__ float sigmoid_f(float z) {
    return 1.0f / (1.0f + expf(-z));
}
__device__ __forceinline__ float silu_f(float z) {
    return z * sigmoid_f(z);
}

// ---------------- PTX wrappers --------------------------------------------------------
__device__ __forceinline__ unsigned smem_u32(const void* p) {
    unsigned a;
    asm("{ .reg .u64 t; cvta.to.shared.u64 t, %1; cvt.u32.u64 %0, t; }"
        : "=r"(a) : "l"(p));
    return a;
}
__device__ __forceinline__ void mbar_init(unsigned addr, unsigned count) {
    asm volatile("mbarrier.init.shared.b64 [%0], %1;" :: "r"(addr), "r"(count) : "memory");
}
__device__ __forceinline__ void mbar_expect_tx(unsigned addr, unsigned bytes) {
    asm volatile("mbarrier.arrive.expect_tx.shared.b64 _, [%0], %1;"
                 :: "r"(addr), "r"(bytes) : "memory");
}
__device__ __forceinline__ void bulk_g2s(unsigned dst, const void* src,
                                         unsigned bytes, unsigned mbar) {
    asm volatile("cp.async.bulk.shared::cluster.global.mbarrier::complete_tx::bytes "
                 "[%0], [%1], %2, [%3];"
                 :: "r"(dst), "l"(src), "r"(bytes), "r"(mbar) : "memory");
}
__device__ __forceinline__ void mbar_wait(unsigned addr, unsigned parity) {
    unsigned done;
    asm volatile(
        "{\n\t.reg .pred p;\n\t"
        "mbarrier.try_wait.parity.acquire.cta.shared::cta.b64 p, [%1], %2;\n\t"
        "selp.b32 %0, 1, 0, p;\n\t}"
        : "=r"(done) : "r"(addr), "r"(parity) : "memory");
    if (!done) {
        asm volatile(
            "{\n\t.reg .pred P1;\n\t"
            "WAIT_LOOP_%=:\n\t"
            "mbarrier.try_wait.parity.acquire.cta.shared::cta.b64 P1, [%0], %1, 0x989680;\n\t"
            "@P1 bra.uni WAIT_DONE_%=;\n\t"
            "bra.uni WAIT_LOOP_%=;\n\t"
            "WAIT_DONE_%=:\n\t}"
            :: "r"(addr), "r"(parity) : "memory");
    }
}

// ---------------- kernel 1: sequential prep (1 block, 64 threads) ---------------------
__global__ void prep_kernel(
    const float* __restrict__ wl,
    const float* __restrict__ Tp,  const float* __restrict__ Pp,
    const float* __restrict__ o3p, const float* __restrict__ h2op, const float* __restrict__ co2p,
    const float* __restrict__ mw1, const float* __restrict__ mb1,
    const float* __restrict__ mw2, const float* __restrict__ mb2,
    const float* __restrict__ cw1, const float* __restrict__ cb1,
    const float* __restrict__ cw2, const float* __restrict__ cb2)
{
    __shared__ float s_nu0[10], s_is[10], s_y[10], s_amp[10];
    __shared__ float s_h[32], s_mf[10], s_m1[64];

    const int t = threadIdx.x;
    const float T = Tp[0];
    const float P = Pp[0];
    const float invT = 273.15f / (T + 1e-12f);

    if (t < 10) {
        float sT    = c_str[t] * powf(invT, c_tex[t]);
        float gL    = c_wid[t] * (P / (101325.0f + 1e-12f)) * sqrtf(invT);
        float gD    = c_nu0[t] / 299792458.0f *
                      sqrtf(2.0f * 1.380649e-23f * T * 6.02214076e23f / (c_mass[t] + 1e-12f));
        float sigma = gD / (1.1774100f + 1e-12f);
        float conc  = (t < 3) ? o3p[0] : ((t < 6) ? h2op[0] : co2p[0]);
        float is    = 1.0f / (sigma + 1e-12f);
        float yv    = gL * is;
        float amp   = conc * sT / (sigma * 1.7724539f + 1e-12f);
        s_nu0[t] = c_nu0[t];  s_is[t] = is;  s_y[t] = yv;  s_amp[t] = amp;
        g_nu0[t] = c_nu0[t];  g_is[t] = is;  g_y[t] = yv;  g_amp[t] = amp;
    }

    if (t < 32) {
        float z = cb1[t];
        z = fmaf(T / (273.15f + 1e-12f),   cw1[0 * 32 + t], z);
        z = fmaf(P / (101325.0f + 1e-12f), cw1[1 * 32 + t], z);
        z = fmaf(h2op[0],                  cw1[2 * 32 + t], z);
        z = fmaf(1.0f,                     cw1[3 * 32 + t], z);
        float h = silu_f(z);
        s_h[t] = h;
        g_h[t] = h;
    }
    __syncthreads();

    if (t < 8) {
        float w = wl[t];
        float c = 0.0f;
        #pragma unroll
        for (int l = 0; l < 10; l++) {
            float x = (w - s_nu0[l]) * s_is[l];
            c = fmaf(s_amp[l], voigt_core(x, s_y[l]), c);
        }
        float z = cb2[t];
        #pragma unroll
        for (int k = 0; k < 32; k++)
            z = fmaf(s_h[k], cw2[k * N_WL + t], z);
        s_mf[2 + t] = c + softplus_f(z);
    }
    if (t == 0) {
        s_mf[0] = T / (273.15f + 1e-12f);
        s_mf[1] = P / (101325.0f + 1e-12f);
    }
    __syncthreads();

    if (t < 64) {
        float z = mb1[t];
        #pragma unroll
        for (int j = 0; j < 10; j++)
            z = fmaf(s_mf[j], mw1[j * 64 + t], z);
        s_m1[t] = silu_f(z);
    }
    __syncthreads();

    if (t < 64) {
        float z = mb2[t];
        #pragma unroll
        for (int j = 0; j < 64; j++)
            z = fmaf(s_m1[j], mw2[j * 64 + t], z);
        g_m2[t] = silu_f(z);
    }
}

// ---------------- kernel 2: TMA-pipelined streaming pass ------------------------------
// 1024 blocks x 256 threads; each block owns 256 consecutive wavelengths (one float
// column tile, 1KB per matrix row). cp.async.bulk double-buffer (12 rows = 12KB per
// stage) keeps DRAM requests hardware-queued, independent of ptxas scheduling. All
// 1024 blocks resident (8/SM) -> tens of MB in flight -> DRAM-saturated.
__global__ __launch_bounds__(256) void spec_kernel(
    const float* __restrict__ wl,
    const float* __restrict__ cont_w2, const float* __restrict__ cont_b2,
    const float* __restrict__ mix_w3,  const float* __restrict__ mix_b3,
    float* __restrict__ out)
{
    __shared__ __align__(128) float sbuf[2][NR * TILE];   // 2 x 12KB
    __shared__ __align__(8) unsigned long long mbar_full[2];
    __shared__ float s_c[NROWS];
    __shared__ float s_nu0[10], s_is[10], s_y[10], s_amp[10];

    const int t = threadIdx.x;
    const int C0 = blockIdx.x * TILE;        // first float column of this tile
    const int g  = C0 + t;                   // this thread's wavelength index

    if (t < 32)                s_c[t]      = g_h[t];
    else if (t < 96)           s_c[t]      = g_m2[t - 32];
    if (t < 10) { s_nu0[t] = g_nu0[t]; s_is[t] = g_is[t]; s_y[t] = g_y[t]; s_amp[t] = g_amp[t]; }

    unsigned mb0 = smem_u32(&mbar_full[0]);
    unsigned mb1_ = smem_u32(&mbar_full[1]);
    unsigned sb0 = smem_u32(&sbuf[0][0]);
    unsigned sb1 = smem_u32(&sbuf[1][0]);

    if (t == 0) {
        mbar_init(mb0, 1);
        mbar_init(mb1_, 1);
    }
    __syncthreads();

    // ---- prologue: fill both buffers (phases 0 and 1) ----
    if (t == 0) {
        mbar_expect_tx(mb0, STAGE_BYTES);
        #pragma unroll
        for (int r = 0; r < NR; r++) {
            const float* src = cont_w2 + r * N_WL + C0;   // rows 0..11 are cont
            bulk_g2s(sb0 + r * TILE * 4, src, TILE * 4, mb0);
        }
        mbar_expect_tx(mb1_, STAGE_BYTES);
        #pragma unroll
        for (int r = 0; r < NR; r++) {
            int k = NR + r;                               // rows 12..23 are cont
            const float* src = cont_w2 + k * N_WL + C0;
            bulk_g2s(sb1 + r * TILE * 4, src, TILE * 4, mb1_);
        }
    }

    // ---- overlap: Voigt line sum + bias/wavelength loads during first fills ----
    float w = __ldg(wl + g);
    float acc_a = __ldg(cont_b2 + g);   // continuum accumulator
    float acc_z = __ldg(mix_b3 + g);    // mixing accumulator

    float vsum = 0.0f;
    #pragma unroll 1
    for (int l = 0; l < 10; l++) {
        float x = (w - s_nu0[l]) * s_is[l];
        vsum = fmaf(s_amp[l], voigt_core(x, s_y[l]), vsum);
    }

    // ---- pipelined mainloop over 8 phases of 12 rows ----
    int ph[2] = {0, 0};
    #pragma unroll
    for (int p = 0; p < NPH; p++) {
        const int b = p & 1;
        mbar_wait(b ? mb1_ : mb0, ph[b]);
        ph[b] ^= 1;

        const float* buf = sbuf[b];
        #pragma unroll
        for (int r = 0; r < NR; r++) {
            const int k = p * NR + r;
            float v = buf[r * TILE + t];
            if (k < 32) acc_a = fmaf(s_c[k], v, acc_a);
            else        acc_z = fmaf(s_c[k], v, acc_z);
        }
        __syncthreads();   // all reads of buffer b done before refill

        if (p < NPH - 2 && t == 0) {
            const int pn = p + 2;
            unsigned mb = b ? mb1_ : mb0;
            unsigned sb = b ? sb1 : sb0;
            mbar_expect_tx(mb, STAGE_BYTES);
            #pragma unroll
            for (int r = 0; r < NR; r++) {
                const int k = pn * NR + r;
                const float* src = (k < 32) ? (cont_w2 + k * N_WL + C0)
                                            : (mix_w3 + (k - 32) * N_WL + C0);
                bulk_g2s(sb + r * TILE * 4, src, TILE * 4, mb);
            }
        }
    }

    // ---- epilogue ----
    float cross = vsum + softplus_f(acc_a);
    out[g] = cross * (1.0f + 0.1f * (sigmoid_f(acc_z) - 0.5f));
}

// ---------------- launch --------------------------------------------------------------
extern "C" void kernel_launch(void* const* d_in, const int* in_sizes, int n_in,
                              void* d_out, int out_size)
{
    const float* wl   = (const float*)d_in[0];
    const float* Tp   = (const float*)d_in[1];
    const float* Pp   = (const float*)d_in[2];
    const float* o3   = (const float*)d_in[3];
    const float* h2o  = (const float*)d_in[4];
    const float* co2  = (const float*)d_in[5];
    const float* mw1  = (const float*)d_in[6];
    const float* mb1  = (const float*)d_in[7];
    const float* mw2  = (const float*)d_in[8];
    const float* mb2  = (const float*)d_in[9];
    const float* mw3  = (const float*)d_in[10];
    const float* mb3  = (const float*)d_in[11];
    const float* cw1  = (const float*)d_in[12];
    const float* cb1  = (const float*)d_in[13];
    const float* cw2  = (const float*)d_in[14];
    const float* cb2  = (const float*)d_in[15];

    prep_kernel<<<1, 64>>>(wl, Tp, Pp, o3, h2o, co2,
                           mw1, mb1, mw2, mb2, cw1, cb1, cw2, cb2);

    spec_kernel<<<NBLK, 256>>>(
        wl, cw2, cb2, mw3, mb3, (float*)d_out);
}